// round 14
// baseline (speedup 1.0000x reference)
#include <cuda_runtime.h>
#include <cuda_bf16.h>
#include <math.h>
#include <stdint.h>

#define BB 64
#define TT 2048
#define II 512
#define HH 512
#define GG 2048
#define NC 128
#define TPB 256
#define NGRP 4            // batch groups
#define GRP  32           // CTAs (=arrivals) per group

__device__ float         g_gatesx[(size_t)BB * TT * GG];
__device__ __nv_bfloat16 g_xh[(size_t)BB * TT * II];
__device__ __nv_bfloat16 g_xl[(size_t)BB * TT * II];
__device__ __nv_bfloat16 g_wxh[(size_t)GG * II];
__device__ __nv_bfloat16 g_wxl[(size_t)GG * II];
__device__ __nv_bfloat16 g_whh[(size_t)GG * HH];
__device__ __nv_bfloat16 g_whl[(size_t)GG * HH];
// per-group transposed h: row j (0..511) = [16 hi bf16 | 16 lo bf16] = 64B
__device__ __nv_bfloat16 g_hT[2][NGRP][HH * 32];
__device__ unsigned      g_barG[128];         // counters at g*32 (128B apart)

__device__ __forceinline__ uint32_t smem_u32(const void* p) {
    return (uint32_t)__cvta_generic_to_shared(p);
}
#define SWZ(o)   ((o) ^ (((o) >> 3) & 0x70))
#define SWZ64(o) ((o) ^ (((o) >> 3) & 0x30))

__device__ __forceinline__ void ldsm4(uint32_t* r, uint32_t a) {
    asm volatile("ldmatrix.sync.aligned.m8n8.x4.shared.b16 {%0,%1,%2,%3}, [%4];"
                 : "=r"(r[0]), "=r"(r[1]), "=r"(r[2]), "=r"(r[3]) : "r"(a));
}
__device__ __forceinline__ void ldsm4t(uint32_t* r, uint32_t a) {
    asm volatile("ldmatrix.sync.aligned.m8n8.x4.trans.shared.b16 {%0,%1,%2,%3}, [%4];"
                 : "=r"(r[0]), "=r"(r[1]), "=r"(r[2]), "=r"(r[3]) : "r"(a));
}
__device__ __forceinline__ void mma16816(float* c, const uint32_t* a,
                                         uint32_t b0, uint32_t b1) {
    asm volatile(
        "mma.sync.aligned.m16n8k16.row.col.f32.bf16.bf16.f32 "
        "{%0,%1,%2,%3},{%4,%5,%6,%7},{%8,%9},{%0,%1,%2,%3};"
        : "+f"(c[0]), "+f"(c[1]), "+f"(c[2]), "+f"(c[3])
        : "r"(a[0]), "r"(a[1]), "r"(a[2]), "r"(a[3]), "r"(b0), "r"(b1));
}
__device__ __forceinline__ void cpasync16(uint32_t s, const void* g) {
    asm volatile("cp.async.cg.shared.global [%0], [%1], 16;" :: "r"(s), "l"(g));
}
#define CP_COMMIT() asm volatile("cp.async.commit_group;" ::: "memory")
#define CP_WAIT(N)  asm volatile("cp.async.wait_group %0;" :: "n"(N) : "memory")

__device__ __forceinline__ void bar_arrive(unsigned* p) {
    asm volatile("red.release.gpu.global.add.u32 [%0], %1;"
                 :: "l"(p), "r"(1u) : "memory");
}
__device__ __forceinline__ unsigned bar_read(unsigned* p) {
    unsigned v;
    asm volatile("ld.acquire.gpu.global.u32 %0, [%1];" : "=r"(v) : "l"(p)
                 : "memory");
    return v;
}

__global__ void init_k() {
    int i = blockIdx.x * blockDim.x + threadIdx.x;
    if (i < 128) g_barG[i] = 0u;
    for (int k = i; k < NGRP * HH * 32; k += gridDim.x * blockDim.x)
        g_hT[0][0][k] = __float2bfloat16(0.f);
}

// ---- fp32 -> bf16 hi/lo split ----
__device__ __forceinline__ void split4(float4 v, __nv_bfloat16* hi, __nv_bfloat16* lo,
                                       size_t i) {
    __nv_bfloat16 hx = __float2bfloat16(v.x), hy = __float2bfloat16(v.y);
    __nv_bfloat16 hz = __float2bfloat16(v.z), hw = __float2bfloat16(v.w);
    ((__nv_bfloat162*)hi)[2 * i]     = __halves2bfloat162(hx, hy);
    ((__nv_bfloat162*)hi)[2 * i + 1] = __halves2bfloat162(hz, hw);
    ((__nv_bfloat162*)lo)[2 * i] = __halves2bfloat162(
        __float2bfloat16(v.x - __bfloat162float(hx)),
        __float2bfloat16(v.y - __bfloat162float(hy)));
    ((__nv_bfloat162*)lo)[2 * i + 1] = __halves2bfloat162(
        __float2bfloat16(v.z - __bfloat162float(hz)),
        __float2bfloat16(v.w - __bfloat162float(hw)));
}
__global__ void cvt_x_kernel(const float* __restrict__ src) {
    size_t n4 = (size_t)BB * TT * II / 4, st = (size_t)gridDim.x * blockDim.x;
    for (size_t i = blockIdx.x * (size_t)blockDim.x + threadIdx.x; i < n4; i += st)
        split4(((const float4*)src)[i], g_xh, g_xl, i);
}
__global__ void cvt_w_kernel(const float* __restrict__ src) {
    size_t n4 = (size_t)GG * II / 4, st = (size_t)gridDim.x * blockDim.x;
    for (size_t i = blockIdx.x * (size_t)blockDim.x + threadIdx.x; i < n4; i += st)
        split4(((const float4*)src)[i], g_wxh, g_wxl, i);
}
__global__ void cvt_wh_kernel(const float* __restrict__ src) {
    size_t n4 = (size_t)GG * HH / 4, st = (size_t)gridDim.x * blockDim.x;
    for (size_t i = blockIdx.x * (size_t)blockDim.x + threadIdx.x; i < n4; i += st)
        split4(((const float4*)src)[i], g_whh, g_whl, i);
}

// ---- phase 1: mma.sync split-bf16 GEMM (validated R6-R11, unchanged) ----
#define STAGE_BYTES 65536
#define GSMEM_TOTAL (1024 + 2 * STAGE_BYTES)

__global__ __launch_bounds__(256) void gemm_x_mma(
    const float* __restrict__ bx, const float* __restrict__ bh)
{
    extern __shared__ char smem[];
    float* bias_s = (float*)smem;
    char*  tiles  = smem + 1024;
    const uint32_t tb = smem_u32(tiles);
    const int tid = threadIdx.x, lane = tid & 31, w = tid >> 5;
    const int wm = w & 3, wn = w >> 2;
    const int n0 = blockIdx.x * 128;
    const size_t m0 = (size_t)blockIdx.y * 128;

    if (tid < 128) bias_s[tid] = bx[n0 + tid] + bh[n0 + tid];

    auto stage = [&](int c, int buf) {
        uint32_t base = tb + buf * STAGE_BYTES;
#pragma unroll
        for (int i = 0; i < 16; i++) {
            int idx = tid + i * 256;
            int t = idx >> 10, r = (idx >> 3) & 127, ck = idx & 7;
            const __nv_bfloat16* src;
            if (t == 0)      src = g_xh  + (m0 + r) * II;
            else if (t == 1) src = g_xl  + (m0 + r) * II;
            else if (t == 2) src = g_wxh + (size_t)(n0 + r) * II;
            else             src = g_wxl + (size_t)(n0 + r) * II;
            cpasync16(base + t * 16384 + SWZ(r * 128 + ck * 16),
                      (const char*)src + c * 128 + ck * 16);
        }
        CP_COMMIT();
    };

    float acc[2][8][4];
#pragma unroll
    for (int a = 0; a < 2; a++)
#pragma unroll
        for (int bq = 0; bq < 8; bq++)
#pragma unroll
            for (int q = 0; q < 4; q++) acc[a][bq][q] = 0.f;

    stage(0, 0);
    for (int c = 0; c < 8; c++) {
        CP_WAIT(0);
        __syncthreads();
        if (c < 7) stage(c + 1, (c + 1) & 1);

        const uint32_t bA = tb + (c & 1) * STAGE_BYTES;
#pragma unroll
        for (int kk = 0; kk < 4; kk++) {
            const int kb = kk * 32;
            uint32_t ah[2][4], al[2][4];
#pragma unroll
            for (int mt = 0; mt < 2; mt++) {
                int arow = wm * 32 + mt * 16 + (lane & 15);
                uint32_t aoff = SWZ(arow * 128 + kb + (lane >> 4) * 16);
                ldsm4(ah[mt], bA + aoff);
                ldsm4(al[mt], bA + 16384 + aoff);
            }
#pragma unroll
            for (int ng = 0; ng < 4; ng++) {
                int brow = wn * 64 + ng * 16 + ((lane >> 4) & 1) * 8 + (lane & 7);
                uint32_t boff = SWZ(brow * 128 + kb + ((lane >> 3) & 1) * 16);
                uint32_t bhf[4], blf[4];
                ldsm4(bhf, bA + 32768 + boff);
                ldsm4(blf, bA + 49152 + boff);
#pragma unroll
                for (int mt = 0; mt < 2; mt++) {
                    mma16816(acc[mt][ng * 2],     ah[mt], bhf[0], bhf[1]);
                    mma16816(acc[mt][ng * 2],     ah[mt], blf[0], blf[1]);
                    mma16816(acc[mt][ng * 2],     al[mt], bhf[0], bhf[1]);
                    mma16816(acc[mt][ng * 2 + 1], ah[mt], bhf[2], bhf[3]);
                    mma16816(acc[mt][ng * 2 + 1], ah[mt], blf[2], blf[3]);
                    mma16816(acc[mt][ng * 2 + 1], al[mt], bhf[2], bhf[3]);
                }
            }
        }
        __syncthreads();
    }

#pragma unroll
    for (int mt = 0; mt < 2; mt++) {
        size_t row = m0 + wm * 32 + mt * 16 + (lane >> 2);
#pragma unroll
        for (int nf = 0; nf < 8; nf++) {
            int cl = wn * 64 + nf * 8 + (lane & 3) * 2;
            float b0 = bias_s[cl], b1 = bias_s[cl + 1];
            float* p0 = g_gatesx + row * GG + n0 + cl;
            float* p1 = g_gatesx + (row + 8) * GG + n0 + cl;
            *(float2*)p0 = make_float2(acc[mt][nf][0] + b0, acc[mt][nf][1] + b1);
            *(float2*)p1 = make_float2(acc[mt][nf][2] + b0, acc[mt][nf][3] + b1);
        }
    }
}

// ---- phase 2: persistent recurrence, 4 batch-groups x 16 batches ----
// CTA: group g = bx>>5, 16 j-cols (64 gate rows, n = jj*4+gate).
// Warp k-split (64 k each, kt=4); weights in regs (nt=8); M=16 (1 m-tile).
// hT row j = [16 hi | 16 lo] = 64B, SW64 swizzle; staging 4KB/warp/step.
#define SM_H   0                   // 8 warps x 4KB
#define SM_P   32768               // partials: 8w x 16b x 272B = 34816
#define SM_GX  67584               // gates_x: 16 x 272B = 4352
#define SM_OST 71936               // out restage: 16 x 16 fl = 1024
#define RSMEM_TOTAL 133120         // prologue Wh scratch (2 x 64 x 1040) overlaps

__global__ __launch_bounds__(256, 1) void lstm_rec_kernel(float* __restrict__ out)
{
    extern __shared__ char smp[];
    const uint32_t sbase = smem_u32(smp);
    const int tid = threadIdx.x, lane = tid & 31, w = tid >> 5;
    const int g  = blockIdx.x >> 5;
    const int j0 = (blockIdx.x & 31) * 16;
    const int b2 = tid & 15;          // batch within group
    const int jj = tid >> 4;          // 0..15
    unsigned* barp = &g_barG[g * 32];

    // ---- prologue: stage Wh slice (64 rows x 512, hi+lo), stride 1040 ----
#pragma unroll
    for (int i = 0; i < 16; i++) {
        int idx = tid + i * 256;               // 0..4095 uint4
        int n = idx >> 6, cc = idx & 63;       // n = q*4 + gate
        int gate = n & 3, q = n >> 2;
        size_t grow = (size_t)(gate * HH + j0 + q) * HH;
        *(uint4*)(smp + n * 1040 + cc * 16) = *((const uint4*)(g_whh + grow) + cc);
        *(uint4*)(smp + 66560 + n * 1040 + cc * 16) =
            *((const uint4*)(g_whl + grow) + cc);
    }
    __syncthreads();

    // ---- B-frags: warp w owns k [w*64,(w+1)*64); nt = 8 n-groups of 8 ----
    uint32_t Bh[8][4][2], Bl[8][4][2];
    {
        int brow = ((lane >> 4) & 1) * 8 + (lane & 7);
        uint32_t cb = w * 128 + ((lane >> 3) & 1) * 16;
#pragma unroll
        for (int h2 = 0; h2 < 4; h2++) {
#pragma unroll
            for (int kt = 0; kt < 4; kt++) {
                uint32_t off = (h2 * 16 + brow) * 1040 + cb + kt * 32;
                uint32_t r[4];
                ldsm4(r, sbase + off);
                Bh[h2 * 2][kt][0] = r[0];     Bh[h2 * 2][kt][1] = r[1];
                Bh[h2 * 2 + 1][kt][0] = r[2]; Bh[h2 * 2 + 1][kt][1] = r[3];
                ldsm4(r, sbase + 66560 + off);
                Bl[h2 * 2][kt][0] = r[0];     Bl[h2 * 2][kt][1] = r[1];
                Bl[h2 * 2 + 1][kt][0] = r[2]; Bl[h2 * 2 + 1][kt][1] = r[3];
            }
        }
    }
    __syncthreads();   // scratch free

    const int gxb = tid >> 4, gxg = (tid >> 2) & 3, gxq = tid & 3;
    float c = 0.f, h = 0.f;
    unsigned target = GRP;

    for (int t = 0; t < TT; t++) {
        // gates_x prefetch (independent of h)
        float4 gxv = *(const float4*)(g_gatesx +
            ((size_t)(g * 16 + gxb) * TT + t) * GG + (size_t)gxg * HH + j0 + gxq * 4);

        // ---- warp-local cp.async: 4KB contiguous hT slice (SW64) ----
        {
            const char* srch = (const char*)g_hT[t & 1][g] + (size_t)w * 4096;
#pragma unroll
            for (int kt = 0; kt < 4; kt++) {
#pragma unroll
                for (int q = 0; q < 2; q++) {
                    int idx = q * 32 + lane;              // 0..63
                    int r = kt * 16 + (idx >> 2), ck = idx & 3;
                    cpasync16(sbase + SM_H + w * 4096 + SWZ64(r * 64 + ck * 16),
                              srch + r * 64 + ck * 16);
                }
                CP_COMMIT();
            }
        }
        *(float4*)(smp + SM_GX + gxb * 272 + gxg * 64 + gxq * 16) = gxv;

        // ---- MMA, pipelined per kt: acc[nt=8][4], M=16 ----
        float acc[8][4];
#pragma unroll
        for (int nt = 0; nt < 8; nt++)
#pragma unroll
            for (int q = 0; q < 4; q++) acc[nt][q] = 0.f;

        const int khalf = lane >> 4, mhalf = (lane >> 3) & 1, krow = lane & 7;
#define REC_KT(KT, WN)                                                         \
        {                                                                      \
            CP_WAIT(WN);                                                       \
            int row = KT * 16 + khalf * 8 + krow;                              \
            uint32_t Ah[4], Al[4];                                             \
            ldsm4t(Ah, sbase + SM_H + w * 4096 + SWZ64(row * 64 + mhalf * 16));\
            ldsm4t(Al, sbase + SM_H + w * 4096 +                               \
                       SWZ64(row * 64 + 32 + mhalf * 16));                     \
            _Pragma("unroll")                                                  \
            for (int nt = 0; nt < 8; nt++) {                                   \
                mma16816(acc[nt], Ah, Bh[nt][KT][0], Bh[nt][KT][1]);           \
                mma16816(acc[nt], Ah, Bl[nt][KT][0], Bl[nt][KT][1]);           \
                mma16816(acc[nt], Al, Bh[nt][KT][0], Bh[nt][KT][1]);           \
            }                                                                  \
        }
        REC_KT(0, 3) REC_KT(1, 2) REC_KT(2, 1) REC_KT(3, 0)
#undef REC_KT

        // ---- partial store: [w][b(16)][n(64)], row stride 272B ----
        {
            int pg = lane >> 2, ptg = lane & 3;
            uint32_t pbase = SM_P + w * 4352 + ptg * 8;
#pragma unroll
            for (int nt = 0; nt < 8; nt++) {
                *(float2*)(smp + pbase + pg * 272 + nt * 32) =
                    make_float2(acc[nt][0], acc[nt][1]);
                *(float2*)(smp + pbase + (pg + 8) * 272 + nt * 32) =
                    make_float2(acc[nt][2], acc[nt][3]);
            }
        }
        __syncthreads();

        // ---- reduce over 8 warps + pointwise (thread = (b2, jj)) ----
        float4 G = make_float4(0.f, 0.f, 0.f, 0.f);
#pragma unroll
        for (int ww = 0; ww < 8; ww++) {
            float4 p = *(const float4*)(smp + SM_P + ww * 4352 + b2 * 272 + jj * 16);
            G.x += p.x; G.y += p.y; G.z += p.z; G.w += p.w;
        }
        const float* gx = (const float*)(smp + SM_GX) + b2 * 68;
        float xi = G.x + gx[jj];
        float xf = G.y + gx[16 + jj];
        float xg = G.z + gx[32 + jj];
        float xo = G.w + gx[48 + jj];
        float si = __fdividef(1.f, 1.f + __expf(-xi));
        float sf = __fdividef(1.f, 1.f + __expf(-xf));
        float tg2 = tanhf(xg);
        float so = __fdividef(1.f, 1.f + __expf(-xo));
        c = sf * c + si * tg2;
        h = so * tanhf(c);

        // ---- h exchange: row j0+jj, hi byte b2*2 | lo byte 32+b2*2 ----
        {
            __nv_bfloat16 hhi = __float2bfloat16(h);
            __nv_bfloat16 hlo = __float2bfloat16(h - __bfloat162float(hhi));
            char* hrow = (char*)g_hT[(t & 1) ^ 1][g] + (size_t)(j0 + jj) * 64;
            ((__nv_bfloat16*)hrow)[b2] = hhi;
            ((__nv_bfloat16*)(hrow + 32))[b2] = hlo;
            ((float*)(smp + SM_OST))[b2 * 16 + jj] = h;
        }
        __syncthreads();              // orders h STGs before the release-arrive

        if (tid == 0) bar_arrive(barp);

        // coalesced out writes overlap the spin
        if (tid >= 64 && tid < 128) {
            int td = tid - 64, bb = td >> 2, q = td & 3;
            float4 v = *(const float4*)(smp + SM_OST + (bb * 16 + q * 4) * 4);
            *(float4*)(out + ((size_t)(g * 16 + bb) * TT + t) * HH + j0 + q * 4) = v;
        }

        if (lane == 0) { while (bar_read(barp) < target) { } }
        __syncwarp();
        target += GRP;
    }

    // finals: h_n then c_n appended after output
    size_t fin = (size_t)BB * TT * HH;
    int gb = g * 16 + b2;
    out[fin + (size_t)gb * HH + j0 + jj] = h;
    out[fin + (size_t)BB * HH + (size_t)gb * HH + j0 + jj] = c;
}

extern "C" void kernel_launch(void* const* d_in, const int* in_sizes, int n_in,
                              void* d_out, int out_size)
{
    const float* x  = (const float*)d_in[0];
    const float* Wx = (const float*)d_in[1];
    const float* bx = (const float*)d_in[2];
    const float* Wh = (const float*)d_in[3];
    const float* bh = (const float*)d_in[4];
    float* out = (float*)d_out;

    init_k<<<64, 256>>>();
    cvt_x_kernel<<<2048, 256>>>(x);
    cvt_w_kernel<<<64, 256>>>(Wx);
    cvt_wh_kernel<<<64, 256>>>(Wh);

    cudaFuncSetAttribute(gemm_x_mma,
                         cudaFuncAttributeMaxDynamicSharedMemorySize, GSMEM_TOTAL);
    dim3 grid_g(GG / 128, 131072 / 128);
    gemm_x_mma<<<grid_g, 256, GSMEM_TOTAL>>>(bx, bh);

    cudaFuncSetAttribute(lstm_rec_kernel,
                         cudaFuncAttributeMaxDynamicSharedMemorySize, RSMEM_TOTAL);
    lstm_rec_kernel<<<NC, TPB, RSMEM_TOTAL>>>(out);
    (void)in_sizes; (void)n_in; (void)out_size;
}

// round 15
// speedup vs baseline: 1.2258x; 1.2258x over previous
#include <cuda_runtime.h>
#include <cuda_bf16.h>
#include <math.h>
#include <stdint.h>

#define BB 64
#define TT 2048
#define II 512
#define HH 512
#define GG 2048
#define NC 128
#define TPB 256
#define GRP 64            // CTAs per batch-group; arrivals per counter

__device__ float         g_gatesx[(size_t)BB * TT * GG];
__device__ __nv_bfloat16 g_xh[(size_t)BB * TT * II];
__device__ __nv_bfloat16 g_xl[(size_t)BB * TT * II];
__device__ __nv_bfloat16 g_wxh[(size_t)GG * II];
__device__ __nv_bfloat16 g_wxl[(size_t)GG * II];
__device__ __nv_bfloat16 g_whh[(size_t)GG * HH];
__device__ __nv_bfloat16 g_whl[(size_t)GG * HH];
// per-group transposed h: row j (0..511) = [32 hi bf16 | 32 lo bf16] = 128B
__device__ __nv_bfloat16 g_hT[2][2][HH * 64];
__device__ unsigned      g_barG[64];          // counters at [0] and [32]

__device__ __forceinline__ uint32_t smem_u32(const void* p) {
    return (uint32_t)__cvta_generic_to_shared(p);
}
#define SWZ(o) ((o) ^ (((o) >> 3) & 0x70))

__device__ __forceinline__ void ldsm4(uint32_t* r, uint32_t a) {
    asm volatile("ldmatrix.sync.aligned.m8n8.x4.shared.b16 {%0,%1,%2,%3}, [%4];"
                 : "=r"(r[0]), "=r"(r[1]), "=r"(r[2]), "=r"(r[3]) : "r"(a));
}
__device__ __forceinline__ void ldsm4t(uint32_t* r, uint32_t a) {
    asm volatile("ldmatrix.sync.aligned.m8n8.x4.trans.shared.b16 {%0,%1,%2,%3}, [%4];"
                 : "=r"(r[0]), "=r"(r[1]), "=r"(r[2]), "=r"(r[3]) : "r"(a));
}
__device__ __forceinline__ void mma16816(float* c, const uint32_t* a,
                                         uint32_t b0, uint32_t b1) {
    asm volatile(
        "mma.sync.aligned.m16n8k16.row.col.f32.bf16.bf16.f32 "
        "{%0,%1,%2,%3},{%4,%5,%6,%7},{%8,%9},{%0,%1,%2,%3};"
        : "+f"(c[0]), "+f"(c[1]), "+f"(c[2]), "+f"(c[3])
        : "r"(a[0]), "r"(a[1]), "r"(a[2]), "r"(a[3]), "r"(b0), "r"(b1));
}
__device__ __forceinline__ void cpasync16(uint32_t s, const void* g) {
    asm volatile("cp.async.cg.shared.global [%0], [%1], 16;" :: "r"(s), "l"(g));
}
#define CP_COMMIT() asm volatile("cp.async.commit_group;" ::: "memory")
#define CP_WAIT(N)  asm volatile("cp.async.wait_group %0;" :: "n"(N) : "memory")

__device__ __forceinline__ void bar_arrive(unsigned* p) {
    asm volatile("red.release.gpu.global.add.u32 [%0], %1;"
                 :: "l"(p), "r"(1u) : "memory");
}
__device__ __forceinline__ unsigned bar_read(unsigned* p) {
    unsigned v;
    asm volatile("ld.acquire.gpu.global.u32 %0, [%1];" : "=r"(v) : "l"(p)
                 : "memory");
    return v;
}

__global__ void init_k() {
    int i = blockIdx.x * blockDim.x + threadIdx.x;
    if (i < 64) g_barG[i] = 0u;
    for (int k = i; k < 2 * HH * 64; k += gridDim.x * blockDim.x) {
        g_hT[0][0][k] = __float2bfloat16(0.f);   // covers both groups (contiguous)
    }
}

// ---- fp32 -> bf16 hi/lo split ----
__device__ __forceinline__ void split4(float4 v, __nv_bfloat16* hi, __nv_bfloat16* lo,
                                       size_t i) {
    __nv_bfloat16 hx = __float2bfloat16(v.x), hy = __float2bfloat16(v.y);
    __nv_bfloat16 hz = __float2bfloat16(v.z), hw = __float2bfloat16(v.w);
    ((__nv_bfloat162*)hi)[2 * i]     = __halves2bfloat162(hx, hy);
    ((__nv_bfloat162*)hi)[2 * i + 1] = __halves2bfloat162(hz, hw);
    ((__nv_bfloat162*)lo)[2 * i] = __halves2bfloat162(
        __float2bfloat16(v.x - __bfloat162float(hx)),
        __float2bfloat16(v.y - __bfloat162float(hy)));
    ((__nv_bfloat162*)lo)[2 * i + 1] = __halves2bfloat162(
        __float2bfloat16(v.z - __bfloat162float(hz)),
        __float2bfloat16(v.w - __bfloat162float(hw)));
}
__global__ void cvt_x_kernel(const float* __restrict__ src) {
    size_t n4 = (size_t)BB * TT * II / 4, st = (size_t)gridDim.x * blockDim.x;
    for (size_t i = blockIdx.x * (size_t)blockDim.x + threadIdx.x; i < n4; i += st)
        split4(((const float4*)src)[i], g_xh, g_xl, i);
}
// merged Wx + Wh split (both GG x 512 fp32)
__global__ void cvt_w2_kernel(const float* __restrict__ wx,
                              const float* __restrict__ wh) {
    size_t n4 = (size_t)GG * II / 4, st = (size_t)gridDim.x * blockDim.x;
    for (size_t i = blockIdx.x * (size_t)blockDim.x + threadIdx.x; i < n4; i += st) {
        split4(((const float4*)wx)[i], g_wxh, g_wxl, i);
        split4(((const float4*)wh)[i], g_whh, g_whl, i);
    }
}

// ---- phase 1: mma.sync split-bf16 GEMM (validated R6-R11) ----
#define STAGE_BYTES 65536
#define GSMEM_TOTAL (1024 + 2 * STAGE_BYTES)

__global__ __launch_bounds__(256) void gemm_x_mma(
    const float* __restrict__ bx, const float* __restrict__ bh)
{
    extern __shared__ char smem[];
    float* bias_s = (float*)smem;
    char*  tiles  = smem + 1024;
    const uint32_t tb = smem_u32(tiles);
    const int tid = threadIdx.x, lane = tid & 31, w = tid >> 5;
    const int wm = w & 3, wn = w >> 2;
    const int n0 = blockIdx.x * 128;
    const size_t m0 = (size_t)blockIdx.y * 128;

    if (tid < 128) bias_s[tid] = bx[n0 + tid] + bh[n0 + tid];

    auto stage = [&](int c, int buf) {
        uint32_t base = tb + buf * STAGE_BYTES;
#pragma unroll
        for (int i = 0; i < 16; i++) {
            int idx = tid + i * 256;
            int t = idx >> 10, r = (idx >> 3) & 127, ck = idx & 7;
            const __nv_bfloat16* src;
            if (t == 0)      src = g_xh  + (m0 + r) * II;
            else if (t == 1) src = g_xl  + (m0 + r) * II;
            else if (t == 2) src = g_wxh + (size_t)(n0 + r) * II;
            else             src = g_wxl + (size_t)(n0 + r) * II;
            cpasync16(base + t * 16384 + SWZ(r * 128 + ck * 16),
                      (const char*)src + c * 128 + ck * 16);
        }
        CP_COMMIT();
    };

    float acc[2][8][4];
#pragma unroll
    for (int a = 0; a < 2; a++)
#pragma unroll
        for (int bq = 0; bq < 8; bq++)
#pragma unroll
            for (int q = 0; q < 4; q++) acc[a][bq][q] = 0.f;

    stage(0, 0);
    for (int c = 0; c < 8; c++) {
        CP_WAIT(0);
        __syncthreads();
        if (c < 7) stage(c + 1, (c + 1) & 1);

        const uint32_t bA = tb + (c & 1) * STAGE_BYTES;
#pragma unroll
        for (int kk = 0; kk < 4; kk++) {
            const int kb = kk * 32;
            uint32_t ah[2][4], al[2][4];
#pragma unroll
            for (int mt = 0; mt < 2; mt++) {
                int arow = wm * 32 + mt * 16 + (lane & 15);
                uint32_t aoff = SWZ(arow * 128 + kb + (lane >> 4) * 16);
                ldsm4(ah[mt], bA + aoff);
                ldsm4(al[mt], bA + 16384 + aoff);
            }
#pragma unroll
            for (int ng = 0; ng < 4; ng++) {
                int brow = wn * 64 + ng * 16 + ((lane >> 4) & 1) * 8 + (lane & 7);
                uint32_t boff = SWZ(brow * 128 + kb + ((lane >> 3) & 1) * 16);
                uint32_t bhf[4], blf[4];
                ldsm4(bhf, bA + 32768 + boff);
                ldsm4(blf, bA + 49152 + boff);
#pragma unroll
                for (int mt = 0; mt < 2; mt++) {
                    mma16816(acc[mt][ng * 2],     ah[mt], bhf[0], bhf[1]);
                    mma16816(acc[mt][ng * 2],     ah[mt], blf[0], blf[1]);
                    mma16816(acc[mt][ng * 2],     al[mt], bhf[0], bhf[1]);
                    mma16816(acc[mt][ng * 2 + 1], ah[mt], bhf[2], bhf[3]);
                    mma16816(acc[mt][ng * 2 + 1], ah[mt], blf[2], blf[3]);
                    mma16816(acc[mt][ng * 2 + 1], al[mt], bhf[2], bhf[3]);
                }
            }
        }
        __syncthreads();
    }

#pragma unroll
    for (int mt = 0; mt < 2; mt++) {
        size_t row = m0 + wm * 32 + mt * 16 + (lane >> 2);
#pragma unroll
        for (int nf = 0; nf < 8; nf++) {
            int cl = wn * 64 + nf * 8 + (lane & 3) * 2;
            float b0 = bias_s[cl], b1 = bias_s[cl + 1];
            float* p0 = g_gatesx + row * GG + n0 + cl;
            float* p1 = g_gatesx + (row + 8) * GG + n0 + cl;
            *(float2*)p0 = make_float2(acc[mt][nf][0] + b0, acc[mt][nf][1] + b1);
            *(float2*)p1 = make_float2(acc[mt][nf][2] + b0, acc[mt][nf][3] + b1);
        }
    }
}

// ---- phase 2: persistent recurrence, 2 independent batch-groups (R11) ----
#define SM_H   0                   // 8 warps x 8KB (hT slice, swizzled)
#define SM_P   65536               // partials: 8w x 32b x 176B = 45056
#define SM_GX  110592              // gates_x: 32 x 36 fl = 4608
#define SM_OST 115200              // out restage: 32 x 12 fl = 1536
#define RSMEM_TOTAL 116736

__global__ __launch_bounds__(256) void lstm_rec_kernel(float* __restrict__ out)
{
    extern __shared__ char smp[];
    const uint32_t sbase = smem_u32(smp);
    const int tid = threadIdx.x, lane = tid & 31, w = tid >> 5;
    const int g  = blockIdx.x >> 6;
    const int j0 = (blockIdx.x & 63) * 8;
    const int b  = tid & 31;          // batch within group
    const int jj = tid >> 5;          // 0..7 (aliases w; different role)
    unsigned* barp = &g_barG[g * 32];

    // ---- stage Wh slice (32 rows x 512, hi+lo) into scratch (stride 1040) ----
#pragma unroll
    for (int i = 0; i < 8; i++) {
        int idx = tid + i * 256;               // 0..2047 uint4
        int n = idx >> 6, cc = idx & 63;       // n = jj*4 + gate
        int gate = n & 3, q = n >> 2;
        size_t grow = (size_t)(gate * HH + j0 + q) * HH;
        *(uint4*)(smp + n * 1040 + cc * 16) = *((const uint4*)(g_whh + grow) + cc);
        *(uint4*)(smp + 33280 + n * 1040 + cc * 16) =
            *((const uint4*)(g_whl + grow) + cc);
    }
    __syncthreads();

    // ---- B-frags (32-row loader): warp w owns k [w*64,(w+1)*64) ----
    uint32_t Bh[4][4][2], Bl[4][4][2];
    {
        int brow = ((lane >> 4) & 1) * 8 + (lane & 7);
        uint32_t cb = w * 128 + ((lane >> 3) & 1) * 16;
#pragma unroll
        for (int half = 0; half < 2; half++) {
#pragma unroll
            for (int kt = 0; kt < 4; kt++) {
                uint32_t off = (half * 16 + brow) * 1040 + cb + kt * 32;
                uint32_t r[4];
                ldsm4(r, sbase + off);
                Bh[half * 2][kt][0] = r[0];     Bh[half * 2][kt][1] = r[1];
                Bh[half * 2 + 1][kt][0] = r[2]; Bh[half * 2 + 1][kt][1] = r[3];
                ldsm4(r, sbase + 33280 + off);
                Bl[half * 2][kt][0] = r[0];     Bl[half * 2][kt][1] = r[1];
                Bl[half * 2 + 1][kt][0] = r[2]; Bl[half * 2 + 1][kt][1] = r[3];
            }
        }
    }
    __syncthreads();   // scratch free

    const int gxb = tid >> 3, gxg = (tid >> 1) & 3, gxjh = tid & 1;
    float c = 0.f, h = 0.f;
    unsigned target = GRP;

    for (int t = 0; t < TT; t++) {
        // gates_x prefetch (independent of h)
        float4 gxv = *(const float4*)(g_gatesx +
            ((size_t)(g * 32 + gxb) * TT + t) * GG + (size_t)gxg * HH + j0 + gxjh * 4);

        // ---- warp-local cp.async: 8KB contiguous hT slice (hi+lo in-row) ----
        {
            const char* srch = (const char*)g_hT[t & 1][g] + (size_t)w * 8192;
#pragma unroll
            for (int kt = 0; kt < 4; kt++) {
#pragma unroll
                for (int q = 0; q < 4; q++) {
                    int idx = q * 32 + lane;              // 0..127
                    int r = kt * 16 + (idx >> 3), ck = idx & 7;
                    cpasync16(sbase + SM_H + w * 8192 + SWZ(r * 128 + ck * 16),
                              srch + r * 128 + ck * 16);
                }
                CP_COMMIT();
            }
        }
        *(float4*)(smp + SM_GX + gxb * 144 + gxg * 32 + gxjh * 16) = gxv;

        // ---- MMA, pipelined per kt: acc[2 mt][4 nt][4] ----
        float acc[2][4][4];
#pragma unroll
        for (int mt = 0; mt < 2; mt++)
#pragma unroll
            for (int nt = 0; nt < 4; nt++)
#pragma unroll
                for (int q = 0; q < 4; q++) acc[mt][nt][q] = 0.f;

        const int khalf = lane >> 4, mhalf = (lane >> 3) & 1, krow = lane & 7;
#define REC_KT(KT, WN)                                                         \
        {                                                                      \
            CP_WAIT(WN);                                                       \
            _Pragma("unroll")                                                  \
            for (int mt = 0; mt < 2; mt++) {                                   \
                int row = KT * 16 + khalf * 8 + krow;                          \
                uint32_t Ah[4], Al[4];                                         \
                ldsm4t(Ah, sbase + SM_H + w * 8192 +                           \
                           SWZ(row * 128 + mt * 32 + mhalf * 16));             \
                ldsm4t(Al, sbase + SM_H + w * 8192 +                           \
                           SWZ(row * 128 + 64 + mt * 32 + mhalf * 16));        \
                _Pragma("unroll")                                              \
                for (int nt = 0; nt < 4; nt++) {                               \
                    mma16816(acc[mt][nt], Ah, Bh[nt][KT][0], Bh[nt][KT][1]);   \
                    mma16816(acc[mt][nt], Ah, Bl[nt][KT][0], Bl[nt][KT][1]);   \
                    mma16816(acc[mt][nt], Al, Bh[nt][KT][0], Bh[nt][KT][1]);   \
                }                                                              \
            }                                                                  \
        }
        REC_KT(0, 3) REC_KT(1, 2) REC_KT(2, 1) REC_KT(3, 0)
#undef REC_KT

        // ---- partial store: [w][b(32)][n(32)], row stride 176B ----
        {
            int pg = lane >> 2, ptg = lane & 3;
            uint32_t pbase = SM_P + w * 5632 + ptg * 8;
#pragma unroll
            for (int mt = 0; mt < 2; mt++)
#pragma unroll
                for (int nt = 0; nt < 4; nt++) {
                    *(float2*)(smp + pbase + (mt * 16 + pg) * 176 + nt * 32) =
                        make_float2(acc[mt][nt][0], acc[mt][nt][1]);
                    *(float2*)(smp + pbase + (mt * 16 + pg + 8) * 176 + nt * 32) =
                        make_float2(acc[mt][nt][2], acc[mt][nt][3]);
                }
        }
        __syncthreads();

        // ---- reduce over 8 warps + pointwise cell (thread = (b, jj)) ----
        float4 G = make_float4(0.f, 0.f, 0.f, 0.f);
#pragma unroll
        for (int ww = 0; ww < 8; ww++) {
            float4 p = *(const float4*)(smp + SM_P + ww * 5632 + b * 176 + jj * 16);
            G.x += p.x; G.y += p.y; G.z += p.z; G.w += p.w;
        }
        const float* gx = (const float*)(smp + SM_GX) + b * 36;
        float xi = G.x + gx[0 * 8 + jj];
        float xf = G.y + gx[1 * 8 + jj];
        float xg = G.z + gx[2 * 8 + jj];
        float xo = G.w + gx[3 * 8 + jj];
        float si = __fdividef(1.f, 1.f + __expf(-xi));
        float sf = __fdividef(1.f, 1.f + __expf(-xf));
        float tg2 = tanhf(xg);
        float so = __fdividef(1.f, 1.f + __expf(-xo));
        c = sf * c + si * tg2;
        h = so * tanhf(c);

        // ---- h exchange: warp w writes one 128B line (row j0+jj, jj==w) ----
        {
            __nv_bfloat16 hhi = __float2bfloat16(h);
            __nv_bfloat16 hlo = __float2bfloat16(h - __bfloat162float(hhi));
            char* hrow = (char*)g_hT[(t & 1) ^ 1][g] + (size_t)(j0 + jj) * 128;
            ((__nv_bfloat16*)hrow)[b] = hhi;
            ((__nv_bfloat16*)(hrow + 64))[b] = hlo;
            ((float*)(smp + SM_OST))[b * 12 + jj] = h;
        }
        __syncthreads();              // orders h STGs before the release-arrive

        if (tid == 0) bar_arrive(barp);

        // coalesced out writes overlap the spin (not consumed cross-CTA)
        if (tid >= 64 && tid < 96) {
            int bb2 = tid - 64;
            float4 v0 = *(const float4*)(smp + SM_OST + bb2 * 48);
            float4 v1 = *(const float4*)(smp + SM_OST + bb2 * 48 + 16);
            float* op = out + ((size_t)(g * 32 + bb2) * TT + t) * HH + j0;
            *(float4*)op = v0;
            *(float4*)(op + 4) = v1;
        }

        if (lane == 0) { while (bar_read(barp) < target) { } }
        __syncwarp();
        target += GRP;
    }

    // finals: h_n then c_n appended after output
    size_t fin = (size_t)BB * TT * HH;
    int gb = g * 32 + b;
    out[fin + (size_t)gb * HH + j0 + jj] = h;
    out[fin + (size_t)BB * HH + (size_t)gb * HH + j0 + jj] = c;
}

extern "C" void kernel_launch(void* const* d_in, const int* in_sizes, int n_in,
                              void* d_out, int out_size)
{
    const float* x  = (const float*)d_in[0];
    const float* Wx = (const float*)d_in[1];
    const float* bx = (const float*)d_in[2];
    const float* Wh = (const float*)d_in[3];
    const float* bh = (const float*)d_in[4];
    float* out = (float*)d_out;

    init_k<<<32, 256>>>();
    cvt_x_kernel<<<2048, 256>>>(x);
    cvt_w2_kernel<<<64, 256>>>(Wx, Wh);

    cudaFuncSetAttribute(gemm_x_mma,
                         cudaFuncAttributeMaxDynamicSharedMemorySize, GSMEM_TOTAL);
    dim3 grid_g(GG / 128, 131072 / 128);
    gemm_x_mma<<<grid_g, 256, GSMEM_TOTAL>>>(bx, bh);

    cudaFuncSetAttribute(lstm_rec_kernel,
                         cudaFuncAttributeMaxDynamicSharedMemorySize, RSMEM_TOTAL);
    lstm_rec_kernel<<<NC, TPB, RSMEM_TOTAL>>>(out);
    (void)in_sizes; (void)n_in; (void)out_size;
}

// round 16
// speedup vs baseline: 1.3311x; 1.0859x over previous
#include <cuda_runtime.h>
#include <cuda_bf16.h>
#include <cuda_fp16.h>
#include <math.h>
#include <stdint.h>

#define BB 64
#define TT 2048
#define II 512
#define HH 512
#define GG 2048
#define NC 128
#define TPB 256
#define GRP 64            // CTAs per batch-group; arrivals per counter

__device__ float         g_gatesx[(size_t)BB * TT * GG];
__device__ __nv_bfloat16 g_xh[(size_t)BB * TT * II];
__device__ __nv_bfloat16 g_xl[(size_t)BB * TT * II];
__device__ __nv_bfloat16 g_wxh[(size_t)GG * II];
__device__ __nv_bfloat16 g_wxl[(size_t)GG * II];
__device__ __half        g_whh[(size_t)GG * HH];   // Wh fp16 hi
__device__ __half        g_whl[(size_t)GG * HH];   // Wh fp16 lo
// per-group transposed h (fp16): row j (0..511) = 32 b-values = 64B
__device__ __half        g_hT[2][2][HH * 32];
__device__ unsigned      g_barG[64];               // counters at [0] and [32]

__device__ __forceinline__ uint32_t smem_u32(const void* p) {
    return (uint32_t)__cvta_generic_to_shared(p);
}
#define SWZ(o)   ((o) ^ (((o) >> 3) & 0x70))
#define SWZ64(o) ((o) ^ (((o) >> 3) & 0x30))

__device__ __forceinline__ void ldsm4(uint32_t* r, uint32_t a) {
    asm volatile("ldmatrix.sync.aligned.m8n8.x4.shared.b16 {%0,%1,%2,%3}, [%4];"
                 : "=r"(r[0]), "=r"(r[1]), "=r"(r[2]), "=r"(r[3]) : "r"(a));
}
__device__ __forceinline__ void ldsm4t(uint32_t* r, uint32_t a) {
    asm volatile("ldmatrix.sync.aligned.m8n8.x4.trans.shared.b16 {%0,%1,%2,%3}, [%4];"
                 : "=r"(r[0]), "=r"(r[1]), "=r"(r[2]), "=r"(r[3]) : "r"(a));
}
__device__ __forceinline__ void mma16816(float* c, const uint32_t* a,
                                         uint32_t b0, uint32_t b1) {
    asm volatile(
        "mma.sync.aligned.m16n8k16.row.col.f32.bf16.bf16.f32 "
        "{%0,%1,%2,%3},{%4,%5,%6,%7},{%8,%9},{%0,%1,%2,%3};"
        : "+f"(c[0]), "+f"(c[1]), "+f"(c[2]), "+f"(c[3])
        : "r"(a[0]), "r"(a[1]), "r"(a[2]), "r"(a[3]), "r"(b0), "r"(b1));
}
__device__ __forceinline__ void mma16816h(float* c, const uint32_t* a,
                                          uint32_t b0, uint32_t b1) {
    asm volatile(
        "mma.sync.aligned.m16n8k16.row.col.f32.f16.f16.f32 "
        "{%0,%1,%2,%3},{%4,%5,%6,%7},{%8,%9},{%0,%1,%2,%3};"
        : "+f"(c[0]), "+f"(c[1]), "+f"(c[2]), "+f"(c[3])
        : "r"(a[0]), "r"(a[1]), "r"(a[2]), "r"(a[3]), "r"(b0), "r"(b1));
}
__device__ __forceinline__ void cpasync16(uint32_t s, const void* g) {
    asm volatile("cp.async.cg.shared.global [%0], [%1], 16;" :: "r"(s), "l"(g));
}
#define CP_COMMIT() asm volatile("cp.async.commit_group;" ::: "memory")
#define CP_WAIT(N)  asm volatile("cp.async.wait_group %0;" :: "n"(N) : "memory")

__device__ __forceinline__ void bar_arrive(unsigned* p) {
    asm volatile("red.release.gpu.global.add.u32 [%0], %1;"
                 :: "l"(p), "r"(1u) : "memory");
}
__device__ __forceinline__ unsigned bar_read(unsigned* p) {
    unsigned v;
    asm volatile("ld.acquire.gpu.global.u32 %0, [%1];" : "=r"(v) : "l"(p)
                 : "memory");
    return v;
}

__global__ void init_k() {
    int i = blockIdx.x * blockDim.x + threadIdx.x;
    if (i < 64) g_barG[i] = 0u;
    for (int k = i; k < 2 * HH * 32; k += gridDim.x * blockDim.x)
        g_hT[0][0][k] = __float2half(0.f);     // both groups of buffer 0
}

// ---- fp32 -> bf16 hi/lo split ----
__device__ __forceinline__ void split4(float4 v, __nv_bfloat16* hi, __nv_bfloat16* lo,
                                       size_t i) {
    __nv_bfloat16 hx = __float2bfloat16(v.x), hy = __float2bfloat16(v.y);
    __nv_bfloat16 hz = __float2bfloat16(v.z), hw = __float2bfloat16(v.w);
    ((__nv_bfloat162*)hi)[2 * i]     = __halves2bfloat162(hx, hy);
    ((__nv_bfloat162*)hi)[2 * i + 1] = __halves2bfloat162(hz, hw);
    ((__nv_bfloat162*)lo)[2 * i] = __halves2bfloat162(
        __float2bfloat16(v.x - __bfloat162float(hx)),
        __float2bfloat16(v.y - __bfloat162float(hy)));
    ((__nv_bfloat162*)lo)[2 * i + 1] = __halves2bfloat162(
        __float2bfloat16(v.z - __bfloat162float(hz)),
        __float2bfloat16(v.w - __bfloat162float(hw)));
}
// ---- fp32 -> fp16 hi/lo split ----
__device__ __forceinline__ void split4h(float4 v, __half* hi, __half* lo, size_t i) {
    __half hx = __float2half(v.x), hy = __float2half(v.y);
    __half hz = __float2half(v.z), hw = __float2half(v.w);
    ((__half2*)hi)[2 * i]     = __halves2half2(hx, hy);
    ((__half2*)hi)[2 * i + 1] = __halves2half2(hz, hw);
    ((__half2*)lo)[2 * i] = __halves2half2(
        __float2half(v.x - __half2float(hx)),
        __float2half(v.y - __half2float(hy)));
    ((__half2*)lo)[2 * i + 1] = __halves2half2(
        __float2half(v.z - __half2float(hz)),
        __float2half(v.w - __half2float(hw)));
}
__global__ void cvt_x_kernel(const float* __restrict__ src) {
    size_t n4 = (size_t)BB * TT * II / 4, st = (size_t)gridDim.x * blockDim.x;
    for (size_t i = blockIdx.x * (size_t)blockDim.x + threadIdx.x; i < n4; i += st)
        split4(((const float4*)src)[i], g_xh, g_xl, i);
}
// merged Wx (bf16 split) + Wh (fp16 split)
__global__ void cvt_w2_kernel(const float* __restrict__ wx,
                              const float* __restrict__ wh) {
    size_t n4 = (size_t)GG * II / 4, st = (size_t)gridDim.x * blockDim.x;
    for (size_t i = blockIdx.x * (size_t)blockDim.x + threadIdx.x; i < n4; i += st) {
        split4(((const float4*)wx)[i], g_wxh, g_wxl, i);
        split4h(((const float4*)wh)[i], g_whh, g_whl, i);
    }
}

// ---- phase 1: mma.sync split-bf16 GEMM (validated R6-R14, unchanged) ----
#define STAGE_BYTES 65536
#define GSMEM_TOTAL (1024 + 2 * STAGE_BYTES)

__global__ __launch_bounds__(256) void gemm_x_mma(
    const float* __restrict__ bx, const float* __restrict__ bh)
{
    extern __shared__ char smem[];
    float* bias_s = (float*)smem;
    char*  tiles  = smem + 1024;
    const uint32_t tb = smem_u32(tiles);
    const int tid = threadIdx.x, lane = tid & 31, w = tid >> 5;
    const int wm = w & 3, wn = w >> 2;
    const int n0 = blockIdx.x * 128;
    const size_t m0 = (size_t)blockIdx.y * 128;

    if (tid < 128) bias_s[tid] = bx[n0 + tid] + bh[n0 + tid];

    auto stage = [&](int c, int buf) {
        uint32_t base = tb + buf * STAGE_BYTES;
#pragma unroll
        for (int i = 0; i < 16; i++) {
            int idx = tid + i * 256;
            int t = idx >> 10, r = (idx >> 3) & 127, ck = idx & 7;
            const __nv_bfloat16* src;
            if (t == 0)      src = g_xh  + (m0 + r) * II;
            else if (t == 1) src = g_xl  + (m0 + r) * II;
            else if (t == 2) src = g_wxh + (size_t)(n0 + r) * II;
            else             src = g_wxl + (size_t)(n0 + r) * II;
            cpasync16(base + t * 16384 + SWZ(r * 128 + ck * 16),
                      (const char*)src + c * 128 + ck * 16);
        }
        CP_COMMIT();
    };

    float acc[2][8][4];
#pragma unroll
    for (int a = 0; a < 2; a++)
#pragma unroll
        for (int bq = 0; bq < 8; bq++)
#pragma unroll
            for (int q = 0; q < 4; q++) acc[a][bq][q] = 0.f;

    stage(0, 0);
    for (int c = 0; c < 8; c++) {
        CP_WAIT(0);
        __syncthreads();
        if (c < 7) stage(c + 1, (c + 1) & 1);

        const uint32_t bA = tb + (c & 1) * STAGE_BYTES;
#pragma unroll
        for (int kk = 0; kk < 4; kk++) {
            const int kb = kk * 32;
            uint32_t ah[2][4], al[2][4];
#pragma unroll
            for (int mt = 0; mt < 2; mt++) {
                int arow = wm * 32 + mt * 16 + (lane & 15);
                uint32_t aoff = SWZ(arow * 128 + kb + (lane >> 4) * 16);
                ldsm4(ah[mt], bA + aoff);
                ldsm4(al[mt], bA + 16384 + aoff);
            }
#pragma unroll
            for (int ng = 0; ng < 4; ng++) {
                int brow = wn * 64 + ng * 16 + ((lane >> 4) & 1) * 8 + (lane & 7);
                uint32_t boff = SWZ(brow * 128 + kb + ((lane >> 3) & 1) * 16);
                uint32_t bhf[4], blf[4];
                ldsm4(bhf, bA + 32768 + boff);
                ldsm4(blf, bA + 49152 + boff);
#pragma unroll
                for (int mt = 0; mt < 2; mt++) {
                    mma16816(acc[mt][ng * 2],     ah[mt], bhf[0], bhf[1]);
                    mma16816(acc[mt][ng * 2],     ah[mt], blf[0], blf[1]);
                    mma16816(acc[mt][ng * 2],     al[mt], bhf[0], bhf[1]);
                    mma16816(acc[mt][ng * 2 + 1], ah[mt], bhf[2], bhf[3]);
                    mma16816(acc[mt][ng * 2 + 1], ah[mt], blf[2], blf[3]);
                    mma16816(acc[mt][ng * 2 + 1], al[mt], bhf[2], bhf[3]);
                }
            }
        }
        __syncthreads();
    }

#pragma unroll
    for (int mt = 0; mt < 2; mt++) {
        size_t row = m0 + wm * 32 + mt * 16 + (lane >> 2);
#pragma unroll
        for (int nf = 0; nf < 8; nf++) {
            int cl = wn * 64 + nf * 8 + (lane & 3) * 2;
            float b0 = bias_s[cl], b1 = bias_s[cl + 1];
            float* p0 = g_gatesx + row * GG + n0 + cl;
            float* p1 = g_gatesx + (row + 8) * GG + n0 + cl;
            *(float2*)p0 = make_float2(acc[mt][nf][0] + b0, acc[mt][nf][1] + b1);
            *(float2*)p1 = make_float2(acc[mt][nf][2] + b0, acc[mt][nf][3] + b1);
        }
    }
}

// ---- phase 2: persistent recurrence, fp16 2-term (h fp16; Wh fp16 hi+lo) ----
// R11 partition: 2 groups x 64 CTAs, CTA = 8 j-cols (32 gate rows), warp k-split.
// hT row j = 32 fp16 b-values = 64B, SW64; staging 4KB/warp/step; 64 MMA/warp.
#define SM_H   0                   // 8 warps x 4KB (hT slice, SW64)
#define SM_P   32768               // partials: 8w x 32b x 176B = 45056
#define SM_GX  77824               // gates_x: 32 x 36 fl = 4608
#define SM_OST 82432               // out restage: 32 x 12 fl = 1536
#define RSMEM_TOTAL 84480          // prologue Wh scratch (2 x 32 x 1040 = 66560) fits

__global__ __launch_bounds__(256) void lstm_rec_kernel(float* __restrict__ out)
{
    extern __shared__ char smp[];
    const uint32_t sbase = smem_u32(smp);
    const int tid = threadIdx.x, lane = tid & 31, w = tid >> 5;
    const int g  = blockIdx.x >> 6;
    const int j0 = (blockIdx.x & 63) * 8;
    const int b  = tid & 31;          // batch within group
    const int jj = tid >> 5;          // 0..7 (aliases w; different role)
    unsigned* barp = &g_barG[g * 32];

    // ---- stage Wh slice (32 rows x 512 fp16, hi+lo), stride 1040 ----
#pragma unroll
    for (int i = 0; i < 8; i++) {
        int idx = tid + i * 256;               // 0..2047 uint4
        int n = idx >> 6, cc = idx & 63;       // n = jj*4 + gate
        int gate = n & 3, q = n >> 2;
        size_t grow = (size_t)(gate * HH + j0 + q) * HH;
        *(uint4*)(smp + n * 1040 + cc * 16) = *((const uint4*)(g_whh + grow) + cc);
        *(uint4*)(smp + 33280 + n * 1040 + cc * 16) =
            *((const uint4*)(g_whl + grow) + cc);
    }
    __syncthreads();

    // ---- B-frags: warp w owns k [w*64,(w+1)*64); nt = 4 n-groups ----
    uint32_t Bh[4][4][2], Bl[4][4][2];
    {
        int brow = ((lane >> 4) & 1) * 8 + (lane & 7);
        uint32_t cb = w * 128 + ((lane >> 3) & 1) * 16;
#pragma unroll
        for (int half = 0; half < 2; half++) {
#pragma unroll
            for (int kt = 0; kt < 4; kt++) {
                uint32_t off = (half * 16 + brow) * 1040 + cb + kt * 32;
                uint32_t r[4];
                ldsm4(r, sbase + off);
                Bh[half * 2][kt][0] = r[0];     Bh[half * 2][kt][1] = r[1];
                Bh[half * 2 + 1][kt][0] = r[2]; Bh[half * 2 + 1][kt][1] = r[3];
                ldsm4(r, sbase + 33280 + off);
                Bl[half * 2][kt][0] = r[0];     Bl[half * 2][kt][1] = r[1];
                Bl[half * 2 + 1][kt][0] = r[2]; Bl[half * 2 + 1][kt][1] = r[3];
            }
        }
    }
    __syncthreads();   // scratch free

    const int gxb = tid >> 3, gxg = (tid >> 1) & 3, gxjh = tid & 1;
    float c = 0.f, h = 0.f;
    unsigned target = GRP;

    for (int t = 0; t < TT; t++) {
        // gates_x prefetch (independent of h)
        float4 gxv = *(const float4*)(g_gatesx +
            ((size_t)(g * 32 + gxb) * TT + t) * GG + (size_t)gxg * HH + j0 + gxjh * 4);

        // ---- warp-local cp.async: 4KB contiguous hT slice (SW64) ----
        {
            const char* srch = (const char*)g_hT[t & 1][g] + (size_t)w * 4096;
#pragma unroll
            for (int kt = 0; kt < 4; kt++) {
#pragma unroll
                for (int q = 0; q < 2; q++) {
                    int idx = q * 32 + lane;              // 0..63
                    int r = kt * 16 + (idx >> 2), ck = idx & 3;
                    cpasync16(sbase + SM_H + w * 4096 + SWZ64(r * 64 + ck * 16),
                              srch + r * 64 + ck * 16);
                }
                CP_COMMIT();
            }
        }
        *(float4*)(smp + SM_GX + gxb * 144 + gxg * 32 + gxjh * 16) = gxv;

        // ---- MMA, pipelined per kt: acc[2 mt][4 nt][4], 2-term fp16 ----
        float acc[2][4][4];
#pragma unroll
        for (int mt = 0; mt < 2; mt++)
#pragma unroll
            for (int nt = 0; nt < 4; nt++)
#pragma unroll
                for (int q = 0; q < 4; q++) acc[mt][nt][q] = 0.f;

        const int khalf = lane >> 4, mhalf = (lane >> 3) & 1, krow = lane & 7;
#define REC_KT(KT, WN)                                                         \
        {                                                                      \
            CP_WAIT(WN);                                                       \
            _Pragma("unroll")                                                  \
            for (int mt = 0; mt < 2; mt++) {                                   \
                int row = KT * 16 + khalf * 8 + krow;                          \
                uint32_t Ah[4];                                                \
                ldsm4t(Ah, sbase + SM_H + w * 4096 +                           \
                           SWZ64(row * 64 + mt * 32 + mhalf * 16));            \
                _Pragma("unroll")                                              \
                for (int nt = 0; nt < 4; nt++) {                               \
                    mma16816h(acc[mt][nt], Ah, Bh[nt][KT][0], Bh[nt][KT][1]);  \
                    mma16816h(acc[mt][nt], Ah, Bl[nt][KT][0], Bl[nt][KT][1]);  \
                }                                                              \
            }                                                                  \
        }
        REC_KT(0, 3) REC_KT(1, 2) REC_KT(2, 1) REC_KT(3, 0)
#undef REC_KT

        // ---- partial store: [w][b(32)][n(32)], row stride 176B ----
        {
            int pg = lane >> 2, ptg = lane & 3;
            uint32_t pbase = SM_P + w * 5632 + ptg * 8;
#pragma unroll
            for (int mt = 0; mt < 2; mt++)
#pragma unroll
                for (int nt = 0; nt < 4; nt++) {
                    *(float2*)(smp + pbase + (mt * 16 + pg) * 176 + nt * 32) =
                        make_float2(acc[mt][nt][0], acc[mt][nt][1]);
                    *(float2*)(smp + pbase + (mt * 16 + pg + 8) * 176 + nt * 32) =
                        make_float2(acc[mt][nt][2], acc[mt][nt][3]);
                }
        }
        __syncthreads();

        // ---- reduce over 8 warps + pointwise cell (thread = (b, jj)) ----
        float4 G = make_float4(0.f, 0.f, 0.f, 0.f);
#pragma unroll
        for (int ww = 0; ww < 8; ww++) {
            float4 p = *(const float4*)(smp + SM_P + ww * 5632 + b * 176 + jj * 16);
            G.x += p.x; G.y += p.y; G.z += p.z; G.w += p.w;
        }
        const float* gx = (const float*)(smp + SM_GX) + b * 36;
        float xi = G.x + gx[0 * 8 + jj];
        float xf = G.y + gx[1 * 8 + jj];
        float xg = G.z + gx[2 * 8 + jj];
        float xo = G.w + gx[3 * 8 + jj];
        float si = __fdividef(1.f, 1.f + __expf(-xi));
        float sf = __fdividef(1.f, 1.f + __expf(-xf));
        float tg2 = tanhf(xg);
        float so = __fdividef(1.f, 1.f + __expf(-xo));
        c = sf * c + si * tg2;
        h = so * tanhf(c);

        // ---- h exchange: warp w writes one 64B row (row j0+jj, jj==w) ----
        {
            __half* hrow = (__half*)((char*)g_hT[(t & 1) ^ 1][g]
                                     + (size_t)(j0 + jj) * 64);
            hrow[b] = __float2half(h);
            ((float*)(smp + SM_OST))[b * 12 + jj] = h;
        }
        __syncthreads();              // orders h STGs before the release-arrive

        if (tid == 0) bar_arrive(barp);

        // coalesced out writes overlap the spin (not consumed cross-CTA)
        if (tid >= 64 && tid < 96) {
            int bb2 = tid - 64;
            float4 v0 = *(const float4*)(smp + SM_OST + bb2 * 48);
            float4 v1 = *(const float4*)(smp + SM_OST + bb2 * 48 + 16);
            float* op = out + ((size_t)(g * 32 + bb2) * TT + t) * HH + j0;
            *(float4*)op = v0;
            *(float4*)(op + 4) = v1;
        }

        if (lane == 0) { while (bar_read(barp) < target) { } }
        __syncwarp();
        target += GRP;
    }

    // finals: h_n then c_n appended after output
    size_t fin = (size_t)BB * TT * HH;
    int gb = g * 32 + b;
    out[fin + (size_t)gb * HH + j0 + jj] = h;
    out[fin + (size_t)BB * HH + (size_t)gb * HH + j0 + jj] = c;
}

extern "C" void kernel_launch(void* const* d_in, const int* in_sizes, int n_in,
                              void* d_out, int out_size)
{
    const float* x  = (const float*)d_in[0];
    const float* Wx = (const float*)d_in[1];
    const float* bx = (const float*)d_in[2];
    const float* Wh = (const float*)d_in[3];
    const float* bh = (const float*)d_in[4];
    float* out = (float*)d_out;

    init_k<<<32, 256>>>();
    cvt_x_kernel<<<2048, 256>>>(x);
    cvt_w2_kernel<<<64, 256>>>(Wx, Wh);

    cudaFuncSetAttribute(gemm_x_mma,
                         cudaFuncAttributeMaxDynamicSharedMemorySize, GSMEM_TOTAL);
    dim3 grid_g(GG / 128, 131072 / 128);
    gemm_x_mma<<<grid_g, 256, GSMEM_TOTAL>>>(bx, bh);

    cudaFuncSetAttribute(lstm_rec_kernel,
                         cudaFuncAttributeMaxDynamicSharedMemorySize, RSMEM_TOTAL);
    lstm_rec_kernel<<<NC, TPB, RSMEM_TOTAL>>>(out);
    (void)in_sizes; (void)n_in; (void)out_size;
}